// round 6
// baseline (speedup 1.0000x reference)
#include <cuda_runtime.h>
#include <math.h>
#include <stdint.h>
#include <stddef.h>

// ============================================================================
// NoisyTopkRouter: fused mma.sync tf32 GEMM (3-way split, 6 terms, dual accum)
//   pre[t, 0:128] = h[t,:] @ [Wl;Wn]^T  at fp32-equivalent precision:
//     a = ah+am+al (exact), b = bh+bm+bl (exact), keep products >= 2^-22:
//     main acc:  ah*bh
//     corr acc:  ah*bm + am*bh + ah*bl + am*bm + al*bh      (merged at end)
//   then per-token softplus / noisy / full softmax / top-k / sparse softmax.
// Output layout (validated): [route_p BS*E | ix-as-float BS*K | full_p BS*E]
// ============================================================================

#define E_FIX 64
#define NN    128        // outputs per token: [logits | noise-preact]
#define MROWS 128        // tokens per CTA
#define KC    32         // K floats per smem chunk
#define AS    36         // smem row stride (floats), conflict-free frag LDS
#define CS    132        // C-dump row stride (floats)
#define NTHR  512

#define A_OFF(b) ((b) * (MROWS * AS))
#define B_OFF(b) (2 * MROWS * AS + (b) * (NN * AS))
#define SMEM_FLOATS (4 * MROWS * AS)          // 18432 floats = 73728 B
#define SMEM_BYTES  (SMEM_FLOATS * 4)         // C dump (128*132 = 67584 B) reuses

typedef unsigned long long u64;

__device__ __forceinline__ uint32_t f2tf(float x) {
    uint32_t u;
    asm("cvt.rna.tf32.f32 %0, %1;" : "=r"(u) : "f"(x));
    return u;
}
// exact 3-way split: v = hi + mi + lo (each tf32-representable)
__device__ __forceinline__ void split3(float v, uint32_t& hi, uint32_t& mi, uint32_t& lo) {
    hi = f2tf(v);
    float r1 = v - __uint_as_float(hi);
    mi = f2tf(r1);
    float r2 = r1 - __uint_as_float(mi);
    lo = f2tf(r2);
}

__device__ __forceinline__ void mma_tf32(float* d, const uint32_t* a, const uint32_t* b) {
    asm("mma.sync.aligned.m16n8k8.row.col.f32.tf32.tf32.f32 "
        "{%0,%1,%2,%3}, {%4,%5,%6,%7}, {%8,%9}, {%0,%1,%2,%3};"
        : "+f"(d[0]), "+f"(d[1]), "+f"(d[2]), "+f"(d[3])
        : "r"(a[0]), "r"(a[1]), "r"(a[2]), "r"(a[3]), "r"(b[0]), "r"(b[1]));
}

__device__ __forceinline__ float softplus_f(float x) {
    return fmaxf(x, 0.0f) + log1pf(expf(-fabsf(x)));
}

// ----------------------------------------------------------------------------
__global__ void __launch_bounds__(NTHR, 1)
router_fused(const float* __restrict__ h,
             const float* __restrict__ Wl,
             const float* __restrict__ Wn,
             const float* __restrict__ bl,
             const float* __restrict__ bn,
             const float* __restrict__ noise,
             float* __restrict__ out,
             int D, int BS, int K)
{
    extern __shared__ float sf[];
    const int tid  = threadIdx.x;
    const int wid  = tid >> 5;
    const int lane = tid & 31;
    const int g    = lane >> 2;         // fragment row-in-group
    const int t    = lane & 3;          // fragment k-col
    const int tokBase = blockIdx.x * MROWS;
    const int mb  = (wid & 7) * 16;     // warp m16 block
    const int nh  = (wid >> 3) * 64;    // warp n-half (0 or 64)

    // ---- gmem->smem assignments: 2 float4 each for A and B per thread ----
    const float* aptr[2]; const float* bptr[2]; int sidx[2];
#pragma unroll
    for (int i = 0; i < 2; ++i) {
        int q = tid + i * NTHR;         // 0..1023
        int row = q >> 3, c4 = q & 7;
        aptr[i] = h + (size_t)(tokBase + row) * D + c4 * 4;
        const float* w = (row < E_FIX) ? (Wl + (size_t)row * D)
                                       : (Wn + (size_t)(row - E_FIX) * D);
        bptr[i] = w + c4 * 4;
        sidx[i] = row * AS + c4 * 4;
    }

    // ---- prologue: chunk 0 ----
    float4 ra[2], rb[2];
#pragma unroll
    for (int i = 0; i < 2; ++i) { ra[i] = *(const float4*)aptr[i]; rb[i] = *(const float4*)bptr[i]; }
#pragma unroll
    for (int i = 0; i < 2; ++i) {
        *(float4*)&sf[A_OFF(0) + sidx[i]] = ra[i];
        *(float4*)&sf[B_OFF(0) + sidx[i]] = rb[i];
    }
    __syncthreads();

    float accM[8][4], accC[8][4];
#pragma unroll
    for (int nt = 0; nt < 8; ++nt)
#pragma unroll
        for (int j = 0; j < 4; ++j) { accM[nt][j] = 0.0f; accC[nt][j] = 0.0f; }

    const int NCH = D / KC;             // 32 chunks
    for (int s = 0; s < NCH; ++s) {
        const int cur = s & 1;
        const bool more = (s + 1) < NCH;
        if (more) {
            const int off = (s + 1) * KC;
#pragma unroll
            for (int i = 0; i < 2; ++i) {
                ra[i] = *(const float4*)(aptr[i] + off);
                rb[i] = *(const float4*)(bptr[i] + off);
            }
        }
        const float* Abuf = sf + A_OFF(cur);
        const float* Bbuf = sf + B_OFF(cur);
#pragma unroll
        for (int kb = 0; kb < KC; kb += 8) {
            // A fragment (m16 x k8), exact 3-way split
            uint32_t ah[4], am[4], al[4];
            {
                float v0 = Abuf[(mb + g)     * AS + kb + t];
                float v1 = Abuf[(mb + g + 8) * AS + kb + t];
                float v2 = Abuf[(mb + g)     * AS + kb + t + 4];
                float v3 = Abuf[(mb + g + 8) * AS + kb + t + 4];
                split3(v0, ah[0], am[0], al[0]);
                split3(v1, ah[1], am[1], al[1]);
                split3(v2, ah[2], am[2], al[2]);
                split3(v3, ah[3], am[3], al[3]);
            }
#pragma unroll
            for (int nt = 0; nt < 8; ++nt) {
                float u0 = Bbuf[(nh + nt * 8 + g) * AS + kb + t];
                float u1 = Bbuf[(nh + nt * 8 + g) * AS + kb + t + 4];
                uint32_t bh[2], bm[2], blo[2];
                split3(u0, bh[0], bm[0], blo[0]);
                split3(u1, bh[1], bm[1], blo[1]);
                // main term
                mma_tf32(accM[nt], ah, bh);
                // correction terms (magnitudes <= 2^-11 of main)
                mma_tf32(accC[nt], ah, bm);
                mma_tf32(accC[nt], am, bh);
                mma_tf32(accC[nt], ah, blo);
                mma_tf32(accC[nt], am, bm);
                mma_tf32(accC[nt], al, bh);
            }
        }
        if (more) {
            const int nxt = cur ^ 1;
#pragma unroll
            for (int i = 0; i < 2; ++i) {
                *(float4*)&sf[A_OFF(nxt) + sidx[i]] = ra[i];
                *(float4*)&sf[B_OFF(nxt) + sidx[i]] = rb[i];
            }
        }
        __syncthreads();
    }

    // ---- merge accumulators, dump C to smem (reuses A/B region) ----
#pragma unroll
    for (int nt = 0; nt < 8; ++nt) {
        const int nc = nh + nt * 8 + 2 * t;
        *(float2*)&sf[(mb + g)     * CS + nc] =
            make_float2(accM[nt][0] + accC[nt][0], accM[nt][1] + accC[nt][1]);
        *(float2*)&sf[(mb + g + 8) * CS + nc] =
            make_float2(accM[nt][2] + accC[nt][2], accM[nt][3] + accC[nt][3]);
    }
    __syncthreads();

    // ---- epilogue: thread tid<128 handles token tokBase+tid (R2 logic) ----
    if (tid < MROWS) {
        const int tok = tokBase + tid;
        const float* pre = sf + tid * CS;
        const float* nzr = noise + (size_t)tok * E_FIX;

        float noisy[E_FIX];
#pragma unroll
        for (int q = 0; q < E_FIX / 4; ++q) {
            float4 lg = *(const float4*)(pre + 4 * q);
            float4 np = *(const float4*)(pre + E_FIX + 4 * q);
            float4 nv = *(const float4*)(nzr + 4 * q);
            float4 b0 = *(const float4*)(bl + 4 * q);
            float4 b1 = *(const float4*)(bn + 4 * q);
            noisy[4*q+0] = lg.x + b0.x + nv.x * softplus_f(np.x + b1.x);
            noisy[4*q+1] = lg.y + b0.y + nv.y * softplus_f(np.y + b1.y);
            noisy[4*q+2] = lg.z + b0.z + nv.z * softplus_f(np.z + b1.z);
            noisy[4*q+3] = lg.w + b0.w + nv.w * softplus_f(np.w + b1.w);
        }

        float m = noisy[0];
#pragma unroll
        for (int e = 1; e < E_FIX; ++e) m = fmaxf(m, noisy[e]);

        // top-K, strict '>' scan (ties -> lowest index, matching lax.top_k)
        int kidx[8]; float kval[8];
        u64 chosen = 0ull;
        for (int j = 0; j < K; ++j) {
            float best = -INFINITY; int bi = 0;
#pragma unroll
            for (int e = 0; e < E_FIX; ++e) {
                bool ok = (((chosen >> e) & 1ull) == 0ull) && (noisy[e] > best);
                best = ok ? noisy[e] : best;
                bi   = ok ? e : bi;
            }
            kidx[j] = bi; kval[j] = best;
            chosen |= (1ull << bi);
        }

        float sum = 0.0f;
#pragma unroll
        for (int e = 0; e < E_FIX; ++e) { float x = expf(noisy[e] - m); noisy[e] = x; sum += x; }
        const float inv = 1.0f / sum;

        float* route = out + (size_t)tok * E_FIX;
        float* ixo   = out + (size_t)BS * E_FIX + (size_t)tok * K;
        float* fullp = out + (size_t)BS * (E_FIX + K) + (size_t)tok * E_FIX;
#pragma unroll
        for (int q = 0; q < 16; ++q) *(float4*)(route + 4 * q) = make_float4(0.f, 0.f, 0.f, 0.f);
#pragma unroll
        for (int q = 0; q < 16; ++q)
            *(float4*)(fullp + 4 * q) = make_float4(noisy[4*q+0] * inv, noisy[4*q+1] * inv,
                                                    noisy[4*q+2] * inv, noisy[4*q+3] * inv);
        const float rm = kval[0];
        float rs = 0.0f, rv[8];
        for (int j = 0; j < K; ++j) { rv[j] = expf(kval[j] - rm); rs += rv[j]; }
        const float rinv = 1.0f / rs;
        for (int j = 0; j < K; ++j) { route[kidx[j]] = rv[j] * rinv; ixo[j] = (float)kidx[j]; }
    }
}

// ----------------------------------------------------------------------------
// Inputs (metadata order): h, Wl, bl, Wn, bn, noise, [top_k]
// ----------------------------------------------------------------------------
extern "C" void kernel_launch(void* const* d_in, const int* in_sizes, int n_in,
                              void* d_out, int out_size) {
    const float* h  = (const float*)d_in[0];
    const float* Wl = (const float*)d_in[1];
    const float* bl = (const float*)d_in[2];
    const float* Wn = (const float*)d_in[3];
    const float* bn = (const float*)d_in[4];
    const float* nz = (const float*)d_in[5];

    const int E = in_sizes[2];                     // 64
    const int D = in_sizes[1] / E;                 // 1024
    const long long BSE = (long long)in_sizes[5];  // B*S*E
    const int BS = (int)(BSE / E);                 // 32768

    int K = (int)(((long long)out_size - 2LL * BSE) / (long long)BS);
    if (K < 1 || K > 8) K = 2;

    cudaFuncSetAttribute(router_fused, cudaFuncAttributeMaxDynamicSharedMemorySize, SMEM_BYTES);
    router_fused<<<BS / MROWS, NTHR, SMEM_BYTES>>>(h, Wl, Wn, bl, bn, nz, (float*)d_out, D, BS, K);
}

// round 7
// speedup vs baseline: 2.1930x; 2.1930x over previous
#include <cuda_runtime.h>
#include <math.h>
#include <stdint.h>
#include <stddef.h>

// ============================================================================
// NoisyTopkRouter: fused bf16x3 (Ootomo) mma.sync GEMM + epilogue.
//   a = a1+a2+a3 (bf16 chunks, exact 24-bit split), same for b.
//   main acc:  a1*b1
//   corr acc:  a1*b2 + a2*b1 (2^-8) + a1*b3 + a2*b2 + a3*b1 (2^-16)
// Pre-pass kernel splits W = [Wl;Wn] once into packed bf16 planes (global).
// A (h) is split once per element at smem-fill time. Inner loop = LDSM + MMA.
// Output layout (validated): [route_p BS*E | ix-as-float BS*K | full_p BS*E]
// ============================================================================

#define E_FIX 64
#define NN    128         // outputs per token
#define MROWS 128         // tokens per CTA
#define KC    32          // K floats per chunk (= 2 k16 MMA steps)
#define NTHR  512
#define CS    132         // C-dump row stride (floats)

// smem planes: u32-packed bf16 pairs, row stride 20 u32 (80B) -> conflict-free
#define RS        20
#define PLANE_U32 (128 * RS)            // 2560 u32 = 10240 B
#define A_BASE_B  0                     // 3 planes A
#define B_BASE_B  (3 * PLANE_U32 * 4)   // 30720
#define PLANES_B  (6 * PLANE_U32 * 4)   // 61440
#define SMEM_BYTES 69632                // max(planes 61440, C dump 128*132*4=67584)

// pre-split B planes, chunk-major: [chunk][plane][row 128][col 16] u32
__device__ uint32_t g_Bp[32 * 3 * 128 * 16];   // 786 KB

typedef unsigned long long u64;

// pack two floats -> bf16x2 (lo = vlo, hi = vhi)
__device__ __forceinline__ uint32_t cvt2(float vhi, float vlo) {
    uint32_t u;
    asm("cvt.rn.bf16x2.f32 %0, %1, %2;" : "=r"(u) : "f"(vhi), "f"(vlo));
    return u;
}
__device__ __forceinline__ float lo_f(uint32_t u) { return __uint_as_float(u << 16); }
__device__ __forceinline__ float hi_f(uint32_t u) { return __uint_as_float(u & 0xFFFF0000u); }

// exact 3-way bf16 split of a float pair -> 3 packed u32
__device__ __forceinline__ void split3p(float vlo, float vhi,
                                        uint32_t& u1, uint32_t& u2, uint32_t& u3) {
    u1 = cvt2(vhi, vlo);
    float r1l = vlo - lo_f(u1), r1h = vhi - hi_f(u1);
    u2 = cvt2(r1h, r1l);
    float r2l = r1l - lo_f(u2), r2h = r1h - hi_f(u2);
    u3 = cvt2(r2h, r2l);
}

__device__ __forceinline__ void ldsm4(uint32_t* r, uint32_t addr) {
    asm volatile("ldmatrix.sync.aligned.m8n8.x4.shared.b16 {%0,%1,%2,%3}, [%4];"
                 : "=r"(r[0]), "=r"(r[1]), "=r"(r[2]), "=r"(r[3]) : "r"(addr));
}
__device__ __forceinline__ void mma_bf16(float* d, const uint32_t* a, const uint32_t* b) {
    asm("mma.sync.aligned.m16n8k16.row.col.f32.bf16.bf16.f32 "
        "{%0,%1,%2,%3}, {%4,%5,%6,%7}, {%8,%9}, {%0,%1,%2,%3};"
        : "+f"(d[0]), "+f"(d[1]), "+f"(d[2]), "+f"(d[3])
        : "r"(a[0]), "r"(a[1]), "r"(a[2]), "r"(a[3]), "r"(b[0]), "r"(b[1]));
}
__device__ __forceinline__ float softplus_f(float x) {
    return fmaxf(x, 0.0f) + log1pf(expf(-fabsf(x)));
}

// ---------------- pre-pass: split W rows into g_Bp planes -------------------
__global__ void __launch_bounds__(512)
bsplit_kernel(const float* __restrict__ Wl, const float* __restrict__ Wn, int D) {
    int idx = blockIdx.x * 512 + threadIdx.x;      // 0..65535 : (row, kpair)
    int row = idx >> 9;                            // 0..127
    int kp  = idx & 511;                           // pair index, k = 2*kp
    const float* W = (row < E_FIX) ? (Wl + (size_t)row * D)
                                   : (Wn + (size_t)(row - E_FIX) * D);
    float v0 = W[2 * kp], v1 = W[2 * kp + 1];
    uint32_t u1, u2, u3;
    split3p(v0, v1, u1, u2, u3);
    int chunk = kp >> 4, col = kp & 15;
    uint32_t* dst = g_Bp + (size_t)chunk * 6144 + row * 16 + col;
    dst[0]    = u1;
    dst[2048] = u2;
    dst[4096] = u3;
}

// ---------------- fused main kernel -----------------------------------------
__global__ void __launch_bounds__(NTHR)
router_fused(const float* __restrict__ h,
             const float* __restrict__ bl,
             const float* __restrict__ bn,
             const float* __restrict__ noise,
             float* __restrict__ out,
             int D, int BS, int K)
{
    extern __shared__ float sf[];
    uint32_t* su = (uint32_t*)sf;
    uint32_t smb;
    asm("{ .reg .u64 t; cvta.to.shared.u64 t, %1; cvt.u32.u64 %0, t; }" : "=r"(smb) : "l"(sf));

    const int tid  = threadIdx.x;
    const int wid  = tid >> 5;
    const int lane = tid & 31;
    const int g    = lane >> 2;
    const int t    = lane & 3;
    const int tokBase = blockIdx.x * MROWS;
    const int mbW = (wid & 3) * 32;      // warp m32 block
    const int nhW = (wid >> 2) * 32;     // warp n32 block

    // ldmatrix per-lane offsets (bytes within a plane)
    const int ti = lane >> 3;
    const int a_off = (((ti & 1) * 8) + (lane & 7)) * 80 + ((ti >> 1) * 16);
    const int b_off = (((ti >> 1) * 8) + (lane & 7)) * 80 + ((ti & 1) * 16);

    // ---- producer assignments ----
    // A: thread -> (row = tid>>2, kq = tid&3): 8 floats at k = kq*8
    const int arow = tid >> 2, akq = tid & 3;
    const float* aptr = h + (size_t)(tokBase + arow) * D + akq * 8;
    uint32_t* a_sts = su + arow * RS + akq * 4;            // +plane*PLANE_U32
    // B: 3 uint4 per thread from g_Bp chunk block (6144 u32)
    // flat uint4 index f4 = tid + j*512 -> u32 f = f4*4
    uint32_t* b_sts_base = su + (B_BASE_B / 4);

    float4 ra0, ra1; uint4 rbv[3];

    // ---- prologue: chunk 0 ----
    ra0 = *(const float4*)(aptr + 0);
    ra1 = *(const float4*)(aptr + 4);
#pragma unroll
    for (int j = 0; j < 3; ++j)
        rbv[j] = *((const uint4*)g_Bp + (tid + j * 512));

    {
        uint32_t p1[4], p2[4], p3[4];
        split3p(ra0.x, ra0.y, p1[0], p2[0], p3[0]);
        split3p(ra0.z, ra0.w, p1[1], p2[1], p3[1]);
        split3p(ra1.x, ra1.y, p1[2], p2[2], p3[2]);
        split3p(ra1.z, ra1.w, p1[3], p2[3], p3[3]);
        *(uint4*)(a_sts + 0 * PLANE_U32) = make_uint4(p1[0], p1[1], p1[2], p1[3]);
        *(uint4*)(a_sts + 1 * PLANE_U32) = make_uint4(p2[0], p2[1], p2[2], p2[3]);
        *(uint4*)(a_sts + 2 * PLANE_U32) = make_uint4(p3[0], p3[1], p3[2], p3[3]);
#pragma unroll
        for (int j = 0; j < 3; ++j) {
            int f = (tid + j * 512) * 4;
            int pl = f >> 11, rem = f & 2047, row = rem >> 4, col = rem & 15;
            *(uint4*)(b_sts_base + pl * PLANE_U32 + row * RS + col) = rbv[j];
        }
    }
    __syncthreads();

    float accM[2][4][4], accC[2][4][4];
#pragma unroll
    for (int mt = 0; mt < 2; ++mt)
#pragma unroll
        for (int nt = 0; nt < 4; ++nt)
#pragma unroll
            for (int j = 0; j < 4; ++j) { accM[mt][nt][j] = 0.f; accC[mt][nt][j] = 0.f; }

    const int NCH = D / KC;   // 32
    for (int s = 0; s < NCH; ++s) {
        const bool more = (s + 1) < NCH;
        if (more) {
            const int off = (s + 1) * KC;
            ra0 = *(const float4*)(aptr + off);
            ra1 = *(const float4*)(aptr + off + 4);
            const uint4* bp = (const uint4*)(g_Bp + (size_t)(s + 1) * 6144);
#pragma unroll
            for (int j = 0; j < 3; ++j) rbv[j] = bp[tid + j * 512];
        }

        // ---- consume: 2 k16 steps ----
#pragma unroll
        for (int kb = 0; kb < 2; ++kb) {
            uint32_t aa[3][2][4];
#pragma unroll
            for (int p = 0; p < 3; ++p)
#pragma unroll
                for (int mt = 0; mt < 2; ++mt)
                    ldsm4(aa[p][mt],
                          smb + p * 10240 + (mbW + mt * 16) * 80 + kb * 32 + a_off);
#pragma unroll
            for (int bt = 0; bt < 2; ++bt) {
                uint32_t bb[3][4];
#pragma unroll
                for (int p = 0; p < 3; ++p)
                    ldsm4(bb[p],
                          smb + B_BASE_B + p * 10240 + (nhW + bt * 16) * 80 + kb * 32 + b_off);
#pragma unroll
                for (int mt = 0; mt < 2; ++mt)
#pragma unroll
                    for (int j = 0; j < 2; ++j) {      // nt = bt*2 + j
                        const int nt = bt * 2 + j;
                        const uint32_t* b1 = bb[0] + 2 * j;
                        const uint32_t* b2 = bb[1] + 2 * j;
                        const uint32_t* b3 = bb[2] + 2 * j;
                        mma_bf16(accM[mt][nt], aa[0][mt], b1);
                        mma_bf16(accC[mt][nt], aa[0][mt], b2);
                        mma_bf16(accC[mt][nt], aa[1][mt], b1);
                        mma_bf16(accC[mt][nt], aa[0][mt], b3);
                        mma_bf16(accC[mt][nt], aa[1][mt], b2);
                        mma_bf16(accC[mt][nt], aa[2][mt], b1);
                    }
            }
        }
        __syncthreads();

        if (more) {
            uint32_t p1[4], p2[4], p3[4];
            split3p(ra0.x, ra0.y, p1[0], p2[0], p3[0]);
            split3p(ra0.z, ra0.w, p1[1], p2[1], p3[1]);
            split3p(ra1.x, ra1.y, p1[2], p2[2], p3[2]);
            split3p(ra1.z, ra1.w, p1[3], p2[3], p3[3]);
            *(uint4*)(a_sts + 0 * PLANE_U32) = make_uint4(p1[0], p1[1], p1[2], p1[3]);
            *(uint4*)(a_sts + 1 * PLANE_U32) = make_uint4(p2[0], p2[1], p2[2], p2[3]);
            *(uint4*)(a_sts + 2 * PLANE_U32) = make_uint4(p3[0], p3[1], p3[2], p3[3]);
#pragma unroll
            for (int j = 0; j < 3; ++j) {
                int f = (tid + j * 512) * 4;
                int pl = f >> 11, rem = f & 2047, row = rem >> 4, col = rem & 15;
                *(uint4*)(b_sts_base + pl * PLANE_U32 + row * RS + col) = rbv[j];
            }
            __syncthreads();
        }
    }

    // ---- merge + dump C to smem (reuses plane region) ----
#pragma unroll
    for (int mt = 0; mt < 2; ++mt)
#pragma unroll
        for (int nt = 0; nt < 4; ++nt) {
            const int r0 = mbW + mt * 16 + g;
            const int c  = nhW + nt * 8 + 2 * t;
            *(float2*)&sf[r0 * CS + c] =
                make_float2(accM[mt][nt][0] + accC[mt][nt][0],
                            accM[mt][nt][1] + accC[mt][nt][1]);
            *(float2*)&sf[(r0 + 8) * CS + c] =
                make_float2(accM[mt][nt][2] + accC[mt][nt][2],
                            accM[mt][nt][3] + accC[mt][nt][3]);
        }
    __syncthreads();

    // ---- epilogue: thread tid<128 handles token tokBase+tid (passed twice) ----
    if (tid < MROWS) {
        const int tok = tokBase + tid;
        const float* pre = sf + tid * CS;
        const float* nzr = noise + (size_t)tok * E_FIX;

        float noisy[E_FIX];
#pragma unroll
        for (int q = 0; q < E_FIX / 4; ++q) {
            float4 lg = *(const float4*)(pre + 4 * q);
            float4 np = *(const float4*)(pre + E_FIX + 4 * q);
            float4 nv = *(const float4*)(nzr + 4 * q);
            float4 b0 = *(const float4*)(bl + 4 * q);
            float4 b1 = *(const float4*)(bn + 4 * q);
            noisy[4*q+0] = lg.x + b0.x + nv.x * softplus_f(np.x + b1.x);
            noisy[4*q+1] = lg.y + b0.y + nv.y * softplus_f(np.y + b1.y);
            noisy[4*q+2] = lg.z + b0.z + nv.z * softplus_f(np.z + b1.z);
            noisy[4*q+3] = lg.w + b0.w + nv.w * softplus_f(np.w + b1.w);
        }

        float m = noisy[0];
#pragma unroll
        for (int e = 1; e < E_FIX; ++e) m = fmaxf(m, noisy[e]);

        int kidx[8]; float kval[8];
        u64 chosen = 0ull;
        for (int j = 0; j < K; ++j) {
            float best = -INFINITY; int bi = 0;
#pragma unroll
            for (int e = 0; e < E_FIX; ++e) {
                bool ok = (((chosen >> e) & 1ull) == 0ull) && (noisy[e] > best);
                best = ok ? noisy[e] : best;
                bi   = ok ? e : bi;
            }
            kidx[j] = bi; kval[j] = best;
            chosen |= (1ull << bi);
        }

        float sum = 0.0f;
#pragma unroll
        for (int e = 0; e < E_FIX; ++e) { float x = expf(noisy[e] - m); noisy[e] = x; sum += x; }
        const float inv = 1.0f / sum;

        float* route = out + (size_t)tok * E_FIX;
        float* ixo   = out + (size_t)BS * E_FIX + (size_t)tok * K;
        float* fullp = out + (size_t)BS * (E_FIX + K) + (size_t)tok * E_FIX;
#pragma unroll
        for (int q = 0; q < 16; ++q) *(float4*)(route + 4 * q) = make_float4(0.f, 0.f, 0.f, 0.f);
#pragma unroll
        for (int q = 0; q < 16; ++q)
            *(float4*)(fullp + 4 * q) = make_float4(noisy[4*q+0] * inv, noisy[4*q+1] * inv,
                                                    noisy[4*q+2] * inv, noisy[4*q+3] * inv);
        const float rm = kval[0];
        float rs = 0.0f, rv[8];
        for (int j = 0; j < K; ++j) { rv[j] = expf(kval[j] - rm); rs += rv[j]; }
        const float rinv = 1.0f / rs;
        for (int j = 0; j < K; ++j) { route[kidx[j]] = rv[j] * rinv; ixo[j] = (float)kidx[j]; }
    }
}

// ----------------------------------------------------------------------------
// Inputs (metadata order): h, Wl, bl, Wn, bn, noise, [top_k]
// ----------------------------------------------------------------------------
extern "C" void kernel_launch(void* const* d_in, const int* in_sizes, int n_in,
                              void* d_out, int out_size) {
    const float* h  = (const float*)d_in[0];
    const float* Wl = (const float*)d_in[1];
    const float* bl = (const float*)d_in[2];
    const float* Wn = (const float*)d_in[3];
    const float* bn = (const float*)d_in[4];
    const float* nz = (const float*)d_in[5];

    const int E = in_sizes[2];                     // 64
    const int D = in_sizes[1] / E;                 // 1024
    const long long BSE = (long long)in_sizes[5];  // B*S*E
    const int BS = (int)(BSE / E);                 // 32768

    int K = (int)(((long long)out_size - 2LL * BSE) / (long long)BS);
    if (K < 1 || K > 8) K = 2;

    bsplit_kernel<<<128, 512>>>(Wl, Wn, D);
    cudaFuncSetAttribute(router_fused, cudaFuncAttributeMaxDynamicSharedMemorySize, SMEM_BYTES);
    router_fused<<<BS / MROWS, NTHR, SMEM_BYTES>>>(h, bl, bn, nz, (float*)d_out, D, BS, K);
}